// round 4
// baseline (speedup 1.0000x reference)
#include <cuda_runtime.h>

// ---------------------------------------------------------------------------
// MaskedBalancedBCELoss — 3-kernel pipeline, MUFU-free hot paths.
//
//  K1: single full read (157 MB, __ldcs streaming). Per-thread u8-packed
//      32-bin histogram of p over negatives (conflict-free, no atomics),
//      positive COUNT only, and ballot-aggregated compaction of candidates
//      (negatives with p>=0.5, plus positives tagged as -p) into per-block
//      regions of global scratch (~27 MB, stays in L2).
//  K2: derives threshold bin T1 from the histogram; reads ONLY the compacted
//      candidates: positive loss sum (tag v<=0), exact loss sum for negative
//      bins > T1, 64-sub-bin count/sum histogram inside bin T1. All logs via
//      FFMA polynomial (no MUFU). Fallback to full re-read if T1 < 16.
//  K3: resolves the sub-bin crossing (mean-interpolated partial sub-bin),
//      writes the scalar, resets globals (graph-replay safe).
// ---------------------------------------------------------------------------

#define NB1 32
#define NB2 64
#define BLK 256
#define GRID_CAP 888           // 148 SMs * 6
#define SCR_SZ (16u << 20)     // 16M floats = 64 MB scratch

__device__ float        g_scr[SCR_SZ];
__device__ unsigned int g_cnt_blk[GRID_CAP];
__device__ unsigned int g_h1[NB1];
__device__ unsigned int g_h2c[NB2];
__device__ float        g_h2s[NB2];
__device__ unsigned int g_pos_cnt;
__device__ double       g_pos_sum;
__device__ double       g_above_sum;

// Cephes-style natural log, pure FMA/ALU (no MUFU). ~1-2 ulp on normals.
__device__ __forceinline__ float fast_log(float x) {
    int   i  = __float_as_int(x);
    int   e  = ((i >> 23) & 0xFF) - 127;
    float m  = __int_as_float((i & 0x007FFFFF) | 0x3F800000);  // [1,2)
    if (m > 1.41421356f) { m *= 0.5f; e += 1; }
    float t  = m - 1.0f;                                       // [-0.293, 0.414]
    float z  = t * t;
    float P  = 7.0376836292e-2f;
    P = P * t - 1.1514610310e-1f;
    P = P * t + 1.1676998740e-1f;
    P = P * t - 1.2420140846e-1f;
    P = P * t + 1.4249322787e-1f;
    P = P * t - 1.6668057665e-1f;
    P = P * t + 2.0000714765e-1f;
    P = P * t - 2.4999993993e-1f;
    P = P * t + 3.3333331174e-1f;
    float fe = (float)e;
    float y  = t * z * P;
    y += fe * -2.12194440e-4f;
    y -= 0.5f * z;
    float r  = t + y;
    r += fe * 0.693359375f;
    return r;
}
__device__ __forceinline__ float pos_loss_f(float p) { return fminf(-fast_log(p), 100.0f); }
__device__ __forceinline__ float neg_loss_f(float p) { return fminf(-fast_log(1.0f - p), 100.0f); }

// ---------------------------------------------------------------------------
// K1
// ---------------------------------------------------------------------------
__global__ void __launch_bounds__(BLK) k1_hist(
    const float4* __restrict__ pred4, const float4* __restrict__ gt4,
    const float4* __restrict__ mask4,
    const float* __restrict__ pred, const float* __restrict__ gt,
    const float* __restrict__ mask, int n, int cap, int use_scr)
{
    __shared__ unsigned int sh[8 * BLK];       // u8-packed 32-bin hist
    __shared__ unsigned int s_binsum[NB1];
    __shared__ unsigned int s_cnt;
    __shared__ unsigned int w_pc[BLK / 32];

    const int tid  = threadIdx.x;
    const int lane = tid & 31;
    const unsigned lt = (1u << lane) - 1u;

#pragma unroll
    for (int w = 0; w < 8; w++) sh[w * BLK + tid] = 0u;
    if (tid < NB1) s_binsum[tid] = 0u;
    if (tid == 0) s_cnt = 0u;
    __syncthreads();

    unsigned int posc = 0;
    const int n4   = n >> 2;
    const int step = gridDim.x * BLK;
    const long long rb = (long long)blockIdx.x * (long long)cap;

    // classify + histogram; returns candidacy, writes tagged value
    auto procE = [&](float p, float g, float mm, bool in, float& v) -> bool {
        bool valid = in && (mm > 0.5f);
        bool ispos = valid && (g > 0.5f);
        bool isneg = valid && !(g > 0.5f);
        posc += ispos ? 1u : 0u;
        if (isneg) {
            int b = min((int)(p * 32.0f), NB1 - 1);
            sh[(b >> 2) * BLK + tid] += 1u << ((b & 3) << 3);
        }
        v = ispos ? -p : p;
        return ispos || (isneg && p >= 0.5f);
    };

    int ibase = blockIdx.x * BLK;
    // main loop: unroll x2 (6 independent LDG.128 per burst)
    while (ibase + step + BLK <= n4) {
        int i0 = ibase + tid, i1 = i0 + step;
        float4 pa = __ldcs(&pred4[i0]), ga = __ldcs(&gt4[i0]), ma = __ldcs(&mask4[i0]);
        float4 pb = __ldcs(&pred4[i1]), gb = __ldcs(&gt4[i1]), mb = __ldcs(&mask4[i1]);
        float v0, v1, v2, v3, v4, v5, v6, v7;
        bool c0 = procE(pa.x, ga.x, ma.x, true, v0);
        bool c1 = procE(pa.y, ga.y, ma.y, true, v1);
        bool c2 = procE(pa.z, ga.z, ma.z, true, v2);
        bool c3 = procE(pa.w, ga.w, ma.w, true, v3);
        bool c4 = procE(pb.x, gb.x, mb.x, true, v4);
        bool c5 = procE(pb.y, gb.y, mb.y, true, v5);
        bool c6 = procE(pb.z, gb.z, mb.z, true, v6);
        bool c7 = procE(pb.w, gb.w, mb.w, true, v7);
        if (use_scr) {
            unsigned m0 = __ballot_sync(0xffffffffu, c0);
            unsigned m1 = __ballot_sync(0xffffffffu, c1);
            unsigned m2 = __ballot_sync(0xffffffffu, c2);
            unsigned m3 = __ballot_sync(0xffffffffu, c3);
            unsigned m4 = __ballot_sync(0xffffffffu, c4);
            unsigned m5 = __ballot_sync(0xffffffffu, c5);
            unsigned m6 = __ballot_sync(0xffffffffu, c6);
            unsigned m7 = __ballot_sync(0xffffffffu, c7);
            unsigned tot = __popc(m0) + __popc(m1) + __popc(m2) + __popc(m3)
                         + __popc(m4) + __popc(m5) + __popc(m6) + __popc(m7);
            unsigned base = 0;
            if (lane == 0 && tot) base = atomicAdd(&s_cnt, tot);
            base = __shfl_sync(0xffffffffu, base, 0);
            unsigned s = base;
            if (c0) g_scr[rb + s + __popc(m0 & lt)] = v0; s += __popc(m0);
            if (c1) g_scr[rb + s + __popc(m1 & lt)] = v1; s += __popc(m1);
            if (c2) g_scr[rb + s + __popc(m2 & lt)] = v2; s += __popc(m2);
            if (c3) g_scr[rb + s + __popc(m3 & lt)] = v3; s += __popc(m3);
            if (c4) g_scr[rb + s + __popc(m4 & lt)] = v4; s += __popc(m4);
            if (c5) g_scr[rb + s + __popc(m5 & lt)] = v5; s += __popc(m5);
            if (c6) g_scr[rb + s + __popc(m6 & lt)] = v6; s += __popc(m6);
            if (c7) g_scr[rb + s + __popc(m7 & lt)] = v7;
        }
        ibase += 2 * step;
    }
    // remainder: block-uniform trips, predicated loads (ballot stays legal)
    for (; ibase < n4; ibase += step) {
        int i = ibase + tid;
        bool in = i < n4;
        float4 pa = in ? __ldcs(&pred4[i]) : make_float4(0.f, 0.f, 0.f, 0.f);
        float4 ga = in ? __ldcs(&gt4[i])   : make_float4(1.f, 1.f, 1.f, 1.f);
        float4 ma = in ? __ldcs(&mask4[i]) : make_float4(0.f, 0.f, 0.f, 0.f);
        float v0, v1, v2, v3;
        bool c0 = procE(pa.x, ga.x, ma.x, in, v0);
        bool c1 = procE(pa.y, ga.y, ma.y, in, v1);
        bool c2 = procE(pa.z, ga.z, ma.z, in, v2);
        bool c3 = procE(pa.w, ga.w, ma.w, in, v3);
        if (use_scr) {
            unsigned m0 = __ballot_sync(0xffffffffu, c0);
            unsigned m1 = __ballot_sync(0xffffffffu, c1);
            unsigned m2 = __ballot_sync(0xffffffffu, c2);
            unsigned m3 = __ballot_sync(0xffffffffu, c3);
            unsigned tot = __popc(m0) + __popc(m1) + __popc(m2) + __popc(m3);
            unsigned base = 0;
            if (lane == 0 && tot) base = atomicAdd(&s_cnt, tot);
            base = __shfl_sync(0xffffffffu, base, 0);
            unsigned s = base;
            if (c0) g_scr[rb + s + __popc(m0 & lt)] = v0; s += __popc(m0);
            if (c1) g_scr[rb + s + __popc(m1 & lt)] = v1; s += __popc(m1);
            if (c2) g_scr[rb + s + __popc(m2 & lt)] = v2; s += __popc(m2);
            if (c3) g_scr[rb + s + __popc(m3 & lt)] = v3;
        }
    }
    // scalar tail (n % 4), block 0 only
    if (blockIdx.x == 0) {
        for (int i = (n4 << 2) + tid; i < n; i += BLK) {
            float p = pred[i], g = gt[i], mm = mask[i];
            bool valid = mm > 0.5f;
            bool ispos = valid && (g > 0.5f);
            bool isneg = valid && !(g > 0.5f);
            if (ispos) posc++;
            if (isneg) {
                int b = min((int)(p * 32.0f), NB1 - 1);
                sh[(b >> 2) * BLK + tid] += 1u << ((b & 3) << 3);
            }
            if (use_scr && (ispos || (isneg && p >= 0.5f))) {
                unsigned o = atomicAdd(&s_cnt, 1u);
                g_scr[rb + o] = ispos ? -p : p;
            }
        }
    }
    __syncthreads();

    // flush per-thread u8 histogram columns (staggered, conflict-free)
    {
        const int b     = tid & 31;
        const int chunk = tid >> 5;
        const int w     = (b >> 2) * BLK;
        const int shft  = (b & 3) << 3;
        unsigned s = 0;
#pragma unroll
        for (int jj = 0; jj < 32; jj++) {
            int j = chunk * 32 + ((jj + b) & 31);
            s += (sh[w + j] >> shft) & 0xFFu;
        }
        if (s) atomicAdd(&s_binsum[b], s);
    }

#pragma unroll
    for (int o = 16; o > 0; o >>= 1)
        posc += __shfl_down_sync(0xffffffffu, posc, o);
    if (lane == 0) w_pc[tid >> 5] = posc;
    __syncthreads();

    if (tid < NB1 && s_binsum[tid]) atomicAdd(&g_h1[tid], s_binsum[tid]);
    if (tid == 0) {
        unsigned pc = 0;
#pragma unroll
        for (int w = 0; w < BLK / 32; w++) pc += w_pc[w];
        if (pc) atomicAdd(&g_pos_cnt, pc);
        g_cnt_blk[blockIdx.x] = s_cnt;
    }
}

// ---------------------------------------------------------------------------
// K2
// ---------------------------------------------------------------------------
__global__ void __launch_bounds__(BLK) k2_refine(
    const float4* __restrict__ pred4, const float4* __restrict__ gt4,
    const float4* __restrict__ mask4,
    const float* __restrict__ pred, const float* __restrict__ gt,
    const float* __restrict__ mask, int n, int cap, int use_scr)
{
    __shared__ int          s_T1;
    __shared__ unsigned int s_h1[NB1];
    __shared__ unsigned int s_c2[NB2];
    __shared__ float        s_s2[NB2];
    __shared__ float        w_as[BLK / 32];
    __shared__ float        w_ps[BLK / 32];

    const int tid = threadIdx.x;
    if (tid < NB1) s_h1[tid] = g_h1[tid];
    if (tid < NB2) { s_c2[tid] = 0u; s_s2[tid] = 0.0f; }
    __syncthreads();

    if (tid == 0) {
        long long negtot = 0;
        for (int i = 0; i < NB1; i++) negtot += (long long)s_h1[i];
        unsigned pos = g_pos_cnt;
        long long k3p = 3LL * (long long)pos;
        long long k = (pos == 0u) ? 0LL : (negtot < k3p ? negtot : k3p);
        int T1 = 1000;
        if (k > 0) {
            long long c = 0;
            for (int i = NB1 - 1; i >= 0; i--) {
                c += (long long)s_h1[i];
                if (c >= k) { T1 = i; break; }
            }
        }
        s_T1 = T1;
    }
    __syncthreads();
    const int T1 = s_T1;

    float asum = 0.0f;   // negative above-threshold loss sum
    float psum = 0.0f;   // positive loss sum
    const bool fast = use_scr && (T1 >= 16);

    auto handle = [&](float v) {
        if (v <= 0.0f) {
            psum += pos_loss_f(-v);
        } else {
            int b = min((int)(v * 32.0f), NB1 - 1);
            if (b > T1) {
                asum += neg_loss_f(v);
            } else if (b == T1) {
                int b2 = (int)(v * 2048.0f) - T1 * 64;
                b2 = max(0, min(b2, NB2 - 1));
                atomicAdd(&s_c2[b2], 1u);
                atomicAdd(&s_s2[b2], neg_loss_f(v));
            }
        }
    };

    if (fast) {
        const long long rb = (long long)blockIdx.x * (long long)cap;
        const unsigned  cnt = g_cnt_blk[blockIdx.x];
        const float4*   scr4 = (const float4*)&g_scr[rb];
        const unsigned  c4 = cnt >> 2;
        for (unsigned j = tid; j < c4; j += BLK) {
            float4 v = scr4[j];
            handle(v.x); handle(v.y); handle(v.z); handle(v.w);
        }
        for (unsigned j = (c4 << 2) + tid; j < cnt; j += BLK)
            handle(g_scr[rb + j]);
    } else if (T1 < NB1) {
        // fallback: full re-read (positives + all negatives handled here)
        const int n4 = n >> 2;
        const int step = gridDim.x * BLK;
        for (int ib = blockIdx.x * BLK; ib < n4; ib += step) {
            int i = ib + tid;
            if (i < n4) {
                float4 p = pred4[i], g = gt4[i], m = mask4[i];
                float ps_[4] = {p.x, p.y, p.z, p.w};
                float gs_[4] = {g.x, g.y, g.z, g.w};
                float ms_[4] = {m.x, m.y, m.z, m.w};
#pragma unroll
                for (int c = 0; c < 4; c++) {
                    if (ms_[c] > 0.5f) {
                        if (gs_[c] > 0.5f) {
                            psum += pos_loss_f(ps_[c]);
                        } else {
                            int b = min((int)(ps_[c] * 32.0f), NB1 - 1);
                            if (b > T1) asum += neg_loss_f(ps_[c]);
                            else if (b == T1) {
                                int b2 = (int)(ps_[c] * 2048.0f) - T1 * 64;
                                b2 = max(0, min(b2, NB2 - 1));
                                atomicAdd(&s_c2[b2], 1u);
                                atomicAdd(&s_s2[b2], neg_loss_f(ps_[c]));
                            }
                        }
                    }
                }
            }
        }
        if (blockIdx.x == 0) {
            for (int i = (n4 << 2) + tid; i < n; i += BLK) {
                float p = pred[i], g = gt[i], mm = mask[i];
                if (mm > 0.5f) {
                    if (g > 0.5f) {
                        psum += pos_loss_f(p);
                    } else {
                        int b = min((int)(p * 32.0f), NB1 - 1);
                        if (b > T1) asum += neg_loss_f(p);
                        else if (b == T1) {
                            int b2 = (int)(p * 2048.0f) - T1 * 64;
                            b2 = max(0, min(b2, NB2 - 1));
                            atomicAdd(&s_c2[b2], 1u);
                            atomicAdd(&s_s2[b2], neg_loss_f(p));
                        }
                    }
                }
            }
        }
    } else if (use_scr) {
        // k == 0: still need positive loss sum from the buffer
        const long long rb = (long long)blockIdx.x * (long long)cap;
        const unsigned  cnt = g_cnt_blk[blockIdx.x];
        for (unsigned j = tid; j < cnt; j += BLK) {
            float v = g_scr[rb + j];
            if (v <= 0.0f) psum += pos_loss_f(-v);
        }
    }

#pragma unroll
    for (int o = 16; o > 0; o >>= 1) {
        asum += __shfl_down_sync(0xffffffffu, asum, o);
        psum += __shfl_down_sync(0xffffffffu, psum, o);
    }
    if ((tid & 31) == 0) { w_as[tid >> 5] = asum; w_ps[tid >> 5] = psum; }
    __syncthreads();

    if (tid < NB2 && s_c2[tid]) {
        atomicAdd(&g_h2c[tid], s_c2[tid]);
        atomicAdd(&g_h2s[tid], s_s2[tid]);
    }
    if (tid == 0) {
        float as = 0.0f, ps = 0.0f;
#pragma unroll
        for (int w = 0; w < BLK / 32; w++) { as += w_as[w]; ps += w_ps[w]; }
        atomicAdd(&g_above_sum, (double)as);
        atomicAdd(&g_pos_sum, (double)ps);
    }
}

// ---------------------------------------------------------------------------
// K3: finalize + reset globals for graph replay
// ---------------------------------------------------------------------------
__global__ void k3_finalize(float* __restrict__ out)
{
    const int tid = threadIdx.x;
    if (tid == 0) {
        long long negtot = 0;
        for (int i = 0; i < NB1; i++) negtot += (long long)g_h1[i];
        unsigned pos = g_pos_cnt;
        long long k3p = 3LL * (long long)pos;
        long long k = (pos == 0u) ? 0LL : (negtot < k3p ? negtot : k3p);

        double nsum = 0.0;
        if (k > 0) {
            long long c = 0, cAbove1 = 0;
            for (int i = NB1 - 1; i >= 0; i--) {
                long long cn = c + (long long)g_h1[i];
                if (cn >= k) { cAbove1 = c; break; }
                c = cn;
            }
            long long r = k - cAbove1;

            long long c2 = 0, cAbove2 = 0;
            double s2above = 0.0;
            int T2 = -1;
            for (int i = NB2 - 1; i >= 0; i--) {
                long long cn = c2 + (long long)g_h2c[i];
                if (cn >= r) { T2 = i; cAbove2 = c2; break; }
                s2above += (double)g_h2s[i];
                c2 = cn;
            }
            double part = 0.0;
            if (T2 >= 0 && g_h2c[T2] > 0u) {
                long long r2 = r - cAbove2;
                if (r2 < 0) r2 = 0;
                part = (double)g_h2s[T2] * ((double)r2 / (double)g_h2c[T2]);
            }
            nsum = g_above_sum + s2above + part;
        }

        double denom = (double)pos + (double)k + 1e-6;
        out[0] = (float)((g_pos_sum + nsum) / denom);
    }
    __syncthreads();

    if (tid < NB1) g_h1[tid] = 0u;
    for (int i = tid; i < NB2; i += blockDim.x) { g_h2c[i] = 0u; g_h2s[i] = 0.0f; }
    if (tid == 0) {
        g_pos_cnt   = 0u;
        g_pos_sum   = 0.0;
        g_above_sum = 0.0;
    }
}

// ---------------------------------------------------------------------------
extern "C" void kernel_launch(void* const* d_in, const int* in_sizes, int n_in,
                              void* d_out, int out_size)
{
    const float* pred = (const float*)d_in[0];
    const float* gt   = (const float*)d_in[1];
    const float* mask = (const float*)d_in[2];
    float* out = (float*)d_out;
    const int n = in_sizes[0];

    const float4* pred4 = (const float4*)pred;
    const float4* gt4   = (const float4*)gt;
    const float4* mask4 = (const float4*)mask;

    int n4 = n >> 2;
    int grid = (n4 + BLK - 1) / BLK;
    if (grid > GRID_CAP) grid = GRID_CAP;
    if (grid < 1) grid = 1;

    int iters = (n4 + grid * BLK - 1) / (grid * BLK);
    long long cap = (long long)iters * BLK * 4 + 8;
    int use_scr = ((long long)grid * cap <= (long long)SCR_SZ) ? 1 : 0;

    k1_hist  <<<grid, BLK>>>(pred4, gt4, mask4, pred, gt, mask, n, (int)cap, use_scr);
    k2_refine<<<grid, BLK>>>(pred4, gt4, mask4, pred, gt, mask, n, (int)cap, use_scr);
    k3_finalize<<<1, 128>>>(out);
}